// round 1
// baseline (speedup 1.0000x reference)
#include <cuda_runtime.h>

#define BB 2
#define TT 5
#define CC 64
#define HH 64
#define WW 64
#define FF 10          // BB*TT frames
#define DD 256         // token dim
#define NTOK 1024      // tokens per frame
#define TN 5120        // TT*NTOK

// ---------------- scratch (device globals; no allocation) ----------------
__device__ float g_uq[BB * DD * TN];                 // [b][d][tok]
__device__ float g_uk[BB * DD * TN];
__device__ float g_uv[BB * DD * TN];
__device__ float g_feat[FF * CC * HH * WW];          // folded attention output
__device__ float g_S[(size_t)BB * TN * TN];          // attention scores (210 MB)

// ---------------- K1: depthwise q & k conv -> token layout ----------------
__global__ void qk_conv_kernel(const float* __restrict__ x,
                               const float* __restrict__ wq, const float* __restrict__ bq,
                               const float* __restrict__ wk, const float* __restrict__ bk) {
    int idx = blockIdx.x * blockDim.x + threadIdx.x;   // over FF*CC*HH*WW
    if (idx >= FF * CC * HH * WW) return;
    int col = idx & 63;
    int row = (idx >> 6) & 63;
    int ch  = (idx >> 12) & 63;
    int f   = idx >> 18;

    const float* xp = x + (((size_t)f * CC + ch) << 12);
    float accq = bq[ch];
    float acck = bk[ch];
    const float* wqp = wq + ch * 9;
    const float* wkp = wk + ch * 9;
    #pragma unroll
    for (int ky = 0; ky < 3; ky++) {
        int r = row + ky - 1;
        if (r < 0 || r >= HH) continue;
        #pragma unroll
        for (int kx = 0; kx < 3; kx++) {
            int c2 = col + kx - 1;
            if (c2 < 0 || c2 >= WW) continue;
            float v = xp[(r << 6) + c2];
            accq += v * wqp[ky * 3 + kx];
            acck += v * wkp[ky * 3 + kx];
        }
    }
    int b = f / TT, t = f % TT;
    int hh = row >> 1, ph = row & 1, ww = col >> 1, pw = col & 1;
    int dch = ch * 4 + ph * 2 + pw;
    int tok = t * NTOK + hh * 32 + ww;
    size_t o = ((size_t)b * DD + dch) * TN + tok;
    g_uq[o] = accq;
    g_uk[o] = acck;
}

// ---------------- dense 3x3 conv (v path & output path) ----------------
#define SPITCH 18
#define CONV_SMEM (CC * SPITCH * SPITCH * 4)

__global__ void dense_conv_kernel(const float* __restrict__ in,  // null -> g_feat
                                  const float* __restrict__ wgt,
                                  const float* __restrict__ bias,
                                  const float* __restrict__ resid,
                                  float* __restrict__ outp,
                                  int tokenized) {
    extern __shared__ float smem[];                 // [CC][18][18]
    const float* inp = in ? in : g_feat;
    int f  = blockIdx.z;
    int y0 = blockIdx.y * 16, x0 = blockIdx.x * 16;
    int tx = threadIdx.x, ty = threadIdx.y;
    int tid = ty * 16 + tx;

    for (int e = tid; e < CC * SPITCH * SPITCH; e += 256) {
        int ci  = e / (SPITCH * SPITCH);
        int rem = e % (SPITCH * SPITCH);
        int ry = rem / SPITCH, rx = rem % SPITCH;
        int gy = y0 + ry - 1, gx = x0 + rx - 1;
        float v = 0.f;
        if (gy >= 0 && gy < HH && gx >= 0 && gx < WW)
            v = inp[(((size_t)f * CC + ci) << 12) + (gy << 6) + gx];
        smem[e] = v;
    }
    __syncthreads();

    int y = y0 + ty, x = x0 + tx;
    const float* sbase = smem + ty * SPITCH + tx;
    int b = f / TT, t = f % TT;
    int hh = y >> 1, ph = y & 1, ww = x >> 1, pw = x & 1;
    int tok = t * NTOK + hh * 32 + ww;

    for (int co = 0; co < CC; co++) {
        float acc = bias[co];
        const float* wp = wgt + co * CC * 9;
        #pragma unroll 4
        for (int ci = 0; ci < CC; ci++) {
            const float* s = sbase + ci * (SPITCH * SPITCH);
            acc += s[0] * wp[0] + s[1] * wp[1] + s[2] * wp[2];
            acc += s[SPITCH] * wp[3] + s[SPITCH + 1] * wp[4] + s[SPITCH + 2] * wp[5];
            acc += s[2 * SPITCH] * wp[6] + s[2 * SPITCH + 1] * wp[7] + s[2 * SPITCH + 2] * wp[8];
            wp += 9;
        }
        if (tokenized) {
            int dch = co * 4 + ph * 2 + pw;
            g_uv[((size_t)b * DD + dch) * TN + tok] = acc;
        } else {
            size_t oi = (((size_t)f * CC + co) << 12) + (y << 6) + x;
            outp[oi] = acc + resid[oi];
        }
    }
}

// ---------------- K2: S = scale * uq^T uk  (TN GEMM, K=256) ----------------
__global__ void gemm_qk_kernel() {
    int bx = blockIdx.x, by = blockIdx.y, b = blockIdx.z;
    __shared__ float As[8][128];
    __shared__ float Bs[8][128];
    const float* A  = g_uq + (size_t)b * DD * TN;
    const float* Bm = g_uk + (size_t)b * DD * TN;
    int tid = threadIdx.x;
    int tx = tid & 15, ty = tid >> 4;
    int lr = tid >> 5, lc = (tid & 31) << 2;

    float acc[8][8];
    #pragma unroll
    for (int i = 0; i < 8; i++)
        #pragma unroll
        for (int j = 0; j < 8; j++) acc[i][j] = 0.f;

    for (int k0 = 0; k0 < DD; k0 += 8) {
        *(float4*)&As[lr][lc] = *(const float4*)&A[(size_t)(k0 + lr) * TN + by * 128 + lc];
        *(float4*)&Bs[lr][lc] = *(const float4*)&Bm[(size_t)(k0 + lr) * TN + bx * 128 + lc];
        __syncthreads();
        #pragma unroll
        for (int kk = 0; kk < 8; kk++) {
            float a[8], bv[8];
            *(float4*)&a[0]  = *(float4*)&As[kk][ty * 8];
            *(float4*)&a[4]  = *(float4*)&As[kk][ty * 8 + 4];
            *(float4*)&bv[0] = *(float4*)&Bs[kk][tx * 8];
            *(float4*)&bv[4] = *(float4*)&Bs[kk][tx * 8 + 4];
            #pragma unroll
            for (int i = 0; i < 8; i++)
                #pragma unroll
                for (int j = 0; j < 8; j++)
                    acc[i][j] += a[i] * bv[j];
        }
        __syncthreads();
    }

    const float scale = 0.0625f;   // d^-0.5, d=256
    size_t base = (size_t)b * TN * TN;
    #pragma unroll
    for (int i = 0; i < 8; i++) {
        size_t m = (size_t)(by * 128 + ty * 8 + i);
        float* op = g_S + base + m * TN + bx * 128 + tx * 8;
        float4 v;
        v.x = acc[i][0] * scale; v.y = acc[i][1] * scale;
        v.z = acc[i][2] * scale; v.w = acc[i][3] * scale;
        *(float4*)op = v;
        v.x = acc[i][4] * scale; v.y = acc[i][5] * scale;
        v.z = acc[i][6] * scale; v.w = acc[i][7] * scale;
        *(float4*)(op + 4) = v;
    }
}

// ---------------- K3: row softmax over S ----------------
__global__ void softmax_kernel() {
    size_t row = blockIdx.x;
    float* p = g_S + row * (size_t)TN;
    int tid = threadIdx.x;
    float vals[20];
    float m = -1e30f;
    #pragma unroll
    for (int i = 0; i < 20; i++) {
        vals[i] = p[tid + (i << 8)];
        m = fmaxf(m, vals[i]);
    }
    __shared__ float red[8];
    #pragma unroll
    for (int o = 16; o; o >>= 1) m = fmaxf(m, __shfl_xor_sync(0xffffffffu, m, o));
    if ((tid & 31) == 0) red[tid >> 5] = m;
    __syncthreads();
    m = red[0];
    #pragma unroll
    for (int i = 1; i < 8; i++) m = fmaxf(m, red[i]);
    __syncthreads();

    float s = 0.f;
    #pragma unroll
    for (int i = 0; i < 20; i++) {
        vals[i] = __expf(vals[i] - m);
        s += vals[i];
    }
    #pragma unroll
    for (int o = 16; o; o >>= 1) s += __shfl_xor_sync(0xffffffffu, s, o);
    if ((tid & 31) == 0) red[tid >> 5] = s;
    __syncthreads();
    s = 0.f;
    #pragma unroll
    for (int i = 0; i < 8; i++) s += red[i];
    float inv = 1.f / s;
    #pragma unroll
    for (int i = 0; i < 20; i++) p[tid + (i << 8)] = vals[i] * inv;
}

// ---------------- K4: ax = S @ uv^T, fused fold into g_feat ----------------
__global__ void gemm_av_kernel() {
    int bx = blockIdx.x;   // N tile (dc), 0..3
    int by = blockIdx.y;   // M tile (token), 0..39
    int b  = blockIdx.z;
    __shared__ float As[16][132];
    __shared__ float Bs[16][68];
    const float* A = g_S  + (size_t)b * TN * TN;   // [TN][TN] row-major
    const float* V = g_uv + (size_t)b * DD * TN;   // [256][TN]
    int tid = threadIdx.x;
    int tx = tid & 15, ty = tid >> 4;
    int ai = tid >> 1, ak = (tid & 1) * 8;
    int bi = tid >> 2, bk = (tid & 3) * 4;
    int i0 = by * 128, n0 = bx * 64;

    float acc[8][4];
    #pragma unroll
    for (int i = 0; i < 8; i++)
        #pragma unroll
        for (int j = 0; j < 4; j++) acc[i][j] = 0.f;

    for (int k0 = 0; k0 < TN; k0 += 16) {
        float4 a0 = *(const float4*)&A[(size_t)(i0 + ai) * TN + k0 + ak];
        float4 a1 = *(const float4*)&A[(size_t)(i0 + ai) * TN + k0 + ak + 4];
        As[ak + 0][ai] = a0.x; As[ak + 1][ai] = a0.y;
        As[ak + 2][ai] = a0.z; As[ak + 3][ai] = a0.w;
        As[ak + 4][ai] = a1.x; As[ak + 5][ai] = a1.y;
        As[ak + 6][ai] = a1.z; As[ak + 7][ai] = a1.w;
        float4 b0 = *(const float4*)&V[(size_t)(n0 + bi) * TN + k0 + bk];
        Bs[bk + 0][bi] = b0.x; Bs[bk + 1][bi] = b0.y;
        Bs[bk + 2][bi] = b0.z; Bs[bk + 3][bi] = b0.w;
        __syncthreads();
        #pragma unroll
        for (int kk = 0; kk < 16; kk++) {
            float a[8], bv[4];
            *(float4*)&a[0]  = *(float4*)&As[kk][ty * 8];
            *(float4*)&a[4]  = *(float4*)&As[kk][ty * 8 + 4];
            *(float4*)&bv[0] = *(float4*)&Bs[kk][tx * 4];
            #pragma unroll
            for (int i = 0; i < 8; i++)
                #pragma unroll
                for (int j = 0; j < 4; j++)
                    acc[i][j] += a[i] * bv[j];
        }
        __syncthreads();
    }

    // fold: ax[b, token, dc] -> feat[f=b*T+t][ch][2hh+ph][2ww+pw]
    #pragma unroll
    for (int i = 0; i < 8; i++) {
        int ig = i0 + ty * 8 + i;
        int t = ig >> 10, r = ig & 1023;
        int hh = r >> 5, ww = r & 31;
        int f = b * TT + t;
        #pragma unroll
        for (int j = 0; j < 4; j++) {
            int dc = n0 + tx * 4 + j;
            int ch = dc >> 2, ph = (dc >> 1) & 1, pw = dc & 1;
            g_feat[(((size_t)f * CC + ch) << 12) + (((hh << 1) + ph) << 6) + ((ww << 1) + pw)] = acc[i][j];
        }
    }
}

// ---------------- launch ----------------
extern "C" void kernel_launch(void* const* d_in, const int* in_sizes, int n_in,
                              void* d_out, int out_size) {
    const float* x  = (const float*)d_in[0];
    const float* wq = (const float*)d_in[1];
    const float* bq = (const float*)d_in[2];
    const float* wk = (const float*)d_in[3];
    const float* bk = (const float*)d_in[4];
    const float* wv = (const float*)d_in[5];
    const float* bv = (const float*)d_in[6];
    const float* wc = (const float*)d_in[7];
    const float* bc = (const float*)d_in[8];
    float* out = (float*)d_out;

    cudaFuncSetAttribute(dense_conv_kernel,
                         cudaFuncAttributeMaxDynamicSharedMemorySize, CONV_SMEM);

    int total = FF * CC * HH * WW;
    qk_conv_kernel<<<total / 256, 256>>>(x, wq, bq, wk, bk);
    dense_conv_kernel<<<dim3(4, 4, FF), dim3(16, 16), CONV_SMEM>>>(x, wv, bv, nullptr, nullptr, 1);
    gemm_qk_kernel<<<dim3(40, 40, BB), 256>>>();
    softmax_kernel<<<BB * TN, 256>>>();
    gemm_av_kernel<<<dim3(4, 40, BB), 256>>>();
    dense_conv_kernel<<<dim3(4, 4, FF), dim3(16, 16), CONV_SMEM>>>(nullptr, wc, bc, x, out, 0);
}

// round 3
// speedup vs baseline: 1.2457x; 1.2457x over previous
#include <cuda_runtime.h>
#include <cuda_bf16.h>
#include <cstdint>

#define BB 2
#define TT 5
#define CC 64
#define HH 64
#define WW 64
#define FF 10          // BB*TT frames
#define DD 256         // token dim
#define NTOK 1024      // tokens per frame
#define TN 5120        // TT*NTOK

typedef __nv_bfloat16 bf16;

// ---------------- scratch (device globals; no allocation) ----------------
__device__ __align__(1024) bf16  g_uq_hi[(size_t)BB * TN * DD];   // [b][tok][d]
__device__ __align__(1024) bf16  g_uq_lo[(size_t)BB * TN * DD];
__device__ __align__(1024) bf16  g_uk_hi[(size_t)BB * TN * DD];
__device__ __align__(1024) bf16  g_uk_lo[(size_t)BB * TN * DD];
__device__ __align__(1024) bf16  g_uv_hi[(size_t)BB * DD * TN];   // [b][d][tok]
__device__ __align__(1024) bf16  g_uv_lo[(size_t)BB * DD * TN];
__device__ __align__(1024) float g_S[(size_t)BB * TN * TN];       // fp32 logits (210MB)
__device__ __align__(1024) bf16  g_S_hi[(size_t)BB * TN * TN];    // softmax probs hi
__device__ __align__(1024) bf16  g_S_lo[(size_t)BB * TN * TN];    // softmax probs lo
__device__ __align__(1024) float g_feat[(size_t)FF * CC * HH * WW];

// ---------------- PTX helpers (sm_80+ feature set ONLY) ----------------
__device__ __forceinline__ uint32_t smem_u32(const void* p) {
    uint32_t a;
    asm("{ .reg .u64 t; cvta.to.shared.u64 t, %1; cvt.u32.u64 %0, t; }" : "=r"(a) : "l"(p));
    return a;
}
#define CP_ASYNC16(saddr, gptr) \
    asm volatile("cp.async.cg.shared.global [%0], [%1], 16;" :: "r"(saddr), "l"(gptr))
#define CP_COMMIT() asm volatile("cp.async.commit_group;" ::: "memory")
#define CP_WAIT0()  asm volatile("cp.async.wait_group 0;" ::: "memory")
#define CP_WAIT1()  asm volatile("cp.async.wait_group 1;" ::: "memory")

#define LDMATRIX_X4(r0, r1, r2, r3, addr) \
    asm volatile("ldmatrix.sync.aligned.m8n8.x4.shared.b16 {%0,%1,%2,%3}, [%4];" \
        : "=r"(r0), "=r"(r1), "=r"(r2), "=r"(r3) : "r"(addr))

#define MMA_BF16(c, a, b) \
    asm volatile("mma.sync.aligned.m16n8k16.row.col.f32.bf16.bf16.f32 " \
        "{%0,%1,%2,%3}, {%4,%5,%6,%7}, {%8,%9}, {%0,%1,%2,%3};" \
        : "+f"((c)[0]), "+f"((c)[1]), "+f"((c)[2]), "+f"((c)[3]) \
        : "r"((a)[0]), "r"((a)[1]), "r"((a)[2]), "r"((a)[3]), "r"((b)[0]), "r"((b)[1]))

// ---------------- K1: depthwise q & k conv -> bf16 hi/lo token layout ----------------
__global__ void qk_conv_kernel(const float* __restrict__ x,
                               const float* __restrict__ wq, const float* __restrict__ bq,
                               const float* __restrict__ wk, const float* __restrict__ bk) {
    int idx = blockIdx.x * blockDim.x + threadIdx.x;
    if (idx >= FF * CC * HH * WW) return;
    int col = idx & 63;
    int row = (idx >> 6) & 63;
    int ch  = (idx >> 12) & 63;
    int f   = idx >> 18;

    const float* xp = x + (((size_t)f * CC + ch) << 12);
    float accq = bq[ch];
    float acck = bk[ch];
    const float* wqp = wq + ch * 9;
    const float* wkp = wk + ch * 9;
    #pragma unroll
    for (int ky = 0; ky < 3; ky++) {
        int r = row + ky - 1;
        if (r < 0 || r >= HH) continue;
        #pragma unroll
        for (int kx = 0; kx < 3; kx++) {
            int c2 = col + kx - 1;
            if (c2 < 0 || c2 >= WW) continue;
            float v = xp[(r << 6) + c2];
            accq += v * wqp[ky * 3 + kx];
            acck += v * wkp[ky * 3 + kx];
        }
    }
    int b = f / TT, t = f % TT;
    int hh = row >> 1, ph = row & 1, ww = col >> 1, pw = col & 1;
    int dch = ch * 4 + ph * 2 + pw;
    int tok = t * NTOK + hh * 32 + ww;
    size_t o = ((size_t)b * TN + tok) * DD + dch;   // token-major (K contiguous)
    bf16 hq = __float2bfloat16(accq);
    bf16 hk = __float2bfloat16(acck);
    g_uq_hi[o] = hq;
    g_uq_lo[o] = __float2bfloat16(accq - __bfloat162float(hq));
    g_uk_hi[o] = hk;
    g_uk_lo[o] = __float2bfloat16(acck - __bfloat162float(hk));
}

// ---------------- dense 3x3 conv (v path & output path) ----------------
#define SPITCH 18
#define CONV_SMEM (CC * SPITCH * SPITCH * 4)

__global__ void dense_conv_kernel(const float* __restrict__ in,  // null -> g_feat
                                  const float* __restrict__ wgt,
                                  const float* __restrict__ bias,
                                  const float* __restrict__ resid,
                                  float* __restrict__ outp,
                                  int tokenized) {
    extern __shared__ float smem[];                 // [CC][18][18]
    const float* inp = in ? in : g_feat;
    int f  = blockIdx.z;
    int y0 = blockIdx.y * 16, x0 = blockIdx.x * 16;
    int tx = threadIdx.x, ty = threadIdx.y;
    int tid = ty * 16 + tx;

    for (int e = tid; e < CC * SPITCH * SPITCH; e += 256) {
        int ci  = e / (SPITCH * SPITCH);
        int rem = e % (SPITCH * SPITCH);
        int ry = rem / SPITCH, rx = rem % SPITCH;
        int gy = y0 + ry - 1, gx = x0 + rx - 1;
        float v = 0.f;
        if (gy >= 0 && gy < HH && gx >= 0 && gx < WW)
            v = inp[(((size_t)f * CC + ci) << 12) + (gy << 6) + gx];
        smem[e] = v;
    }
    __syncthreads();

    int y = y0 + ty, x = x0 + tx;
    const float* sbase = smem + ty * SPITCH + tx;
    int b = f / TT, t = f % TT;
    int hh = y >> 1, ph = y & 1, ww = x >> 1, pw = x & 1;
    int tok = t * NTOK + hh * 32 + ww;

    for (int co = 0; co < CC; co++) {
        float acc = bias[co];
        const float* wp = wgt + co * CC * 9;
        #pragma unroll 4
        for (int ci = 0; ci < CC; ci++) {
            const float* s = sbase + ci * (SPITCH * SPITCH);
            acc += s[0] * wp[0] + s[1] * wp[1] + s[2] * wp[2];
            acc += s[SPITCH] * wp[3] + s[SPITCH + 1] * wp[4] + s[SPITCH + 2] * wp[5];
            acc += s[2 * SPITCH] * wp[6] + s[2 * SPITCH + 1] * wp[7] + s[2 * SPITCH + 2] * wp[8];
            wp += 9;
        }
        if (tokenized) {
            int dch = co * 4 + ph * 2 + pw;
            size_t o = ((size_t)b * DD + dch) * TN + tok;    // d-major ([n][k] k contig)
            bf16 h = __float2bfloat16(acc);
            g_uv_hi[o] = h;
            g_uv_lo[o] = __float2bfloat16(acc - __bfloat162float(h));
        } else {
            size_t oi = (((size_t)f * CC + co) << 12) + (y << 6) + x;
            outp[oi] = acc + resid[oi];
        }
    }
}

// ---------------- split-bf16 HMMA GEMM: D[m][n] = sum_k A[m][k]*B[n][k] ----------------
// 3 segments: Ahi*Bhi, Alo*Bhi, Ahi*Blo.
// MODE 0: A=uq[b][tok][256], B=uk[b][tok][256] -> g_S * 1/16
// MODE 1: A=S_{hi,lo}[b][tok][5120], B=uv[b][256][5120] -> fold into g_feat
#define PITCHB 80                 // smem row pitch in bytes (40 halves) — conflict-free
#define ABUF   10240              // 128 rows * 80B
// layout: A0 @0, A1 @10240, B0 @20480, B1 @30720  (total 40960B static)

template <int MODE>
__global__ void __launch_bounds__(256)
hmma_gemm_kernel() {
    __shared__ __align__(128) char gsm[40960];
    const int tid = threadIdx.x;
    const int lane = tid & 31, wid = tid >> 5;
    const int warp_m = wid & 3, warp_n = wid >> 2;     // 4 x 2 warps
    const int b  = blockIdx.z;
    const int m0 = blockIdx.y * 128;
    const int n0 = blockIdx.x * 128;

    constexpr int KC = (MODE == 0) ? 8 : 160;          // K-chunks (32) per segment
    constexpr int NIT = 3 * KC;
    const size_t aRowB = (MODE == 0) ? DD * 2 : TN * 2;
    const size_t bRowB = (MODE == 0) ? DD * 2 : TN * 2;

    const char *aH, *aL, *bH, *bL;
    if (MODE == 0) {
        size_t ao = ((size_t)b * TN + m0) * DD * 2;
        size_t bo = ((size_t)b * TN + n0) * DD * 2;
        aH = (const char*)g_uq_hi + ao;  aL = (const char*)g_uq_lo + ao;
        bH = (const char*)g_uk_hi + bo;  bL = (const char*)g_uk_lo + bo;
    } else {
        size_t ao = ((size_t)b * TN + m0) * TN * 2;
        size_t bo = ((size_t)b * DD + n0) * TN * 2;
        aH = (const char*)g_S_hi + ao;   aL = (const char*)g_S_lo + ao;
        bH = (const char*)g_uv_hi + bo;  bL = (const char*)g_uv_lo + bo;
    }

    const uint32_t sb = smem_u32(gsm);

    // loader: chunk it -> buffer (it&1)
    auto load_chunk = [&](int it) {
        const int seg = it / KC, kc = it - seg * KC;
        const char* aS = (seg == 1) ? aL : aH;
        const char* bS = (seg == 2) ? bL : bH;
        const uint32_t sa = sb + (it & 1) * ABUF;
        const uint32_t sbm = sb + 20480 + (it & 1) * ABUF;
        const size_t kOff = (size_t)kc * 64;
        #pragma unroll
        for (int u = 0; u < 2; u++) {
            int e = tid + u * 256;
            int row = e >> 2, c16 = (e & 3) << 4;
            CP_ASYNC16(sa + row * PITCHB + c16, aS + (size_t)row * aRowB + kOff + c16);
            CP_ASYNC16(sbm + row * PITCHB + c16, bS + (size_t)row * bRowB + kOff + c16);
        }
        CP_COMMIT();
    };

    float c[2][8][4];
    #pragma unroll
    for (int i = 0; i < 2; i++)
        #pragma unroll
        for (int j = 0; j < 8; j++)
            #pragma unroll
            for (int r = 0; r < 4; r++) c[i][j][r] = 0.f;

    // ldmatrix lane addressing offsets
    const int lrow = lane & 7;                // row within 8
    const int lg   = lane >> 3;               // group 0..3
    const int rowAdd = (lg & 1) * 8;
    const int chunk16 = (lg >> 1) * 16;

    load_chunk(0);

    #pragma unroll 1
    for (int it = 0; it < NIT; it++) {
        if (it + 1 < NIT) load_chunk(it + 1);
        if (it + 1 < NIT) { CP_WAIT1(); } else { CP_WAIT0(); }
        __syncthreads();

        const uint32_t sa = sb + (it & 1) * ABUF;
        const uint32_t sbm = sb + 20480 + (it & 1) * ABUF;
        #pragma unroll
        for (int s = 0; s < 2; s++) {
            const int sByte = s * 32;
            uint32_t a[2][4];
            #pragma unroll
            for (int mi = 0; mi < 2; mi++) {
                int r = warp_m * 32 + mi * 16 + lrow + rowAdd;
                LDMATRIX_X4(a[mi][0], a[mi][1], a[mi][2], a[mi][3],
                            sa + r * PITCHB + sByte + chunk16);
            }
            uint32_t bfr[8][2];
            #pragma unroll
            for (int f = 0; f < 4; f++) {
                int r = warp_n * 64 + f * 16 + lrow + rowAdd;
                uint32_t r0, r1, r2, r3;
                LDMATRIX_X4(r0, r1, r2, r3, sbm + r * PITCHB + sByte + chunk16);
                bfr[2 * f][0] = r0; bfr[2 * f][1] = r2;
                bfr[2 * f + 1][0] = r1; bfr[2 * f + 1][1] = r3;
            }
            #pragma unroll
            for (int mi = 0; mi < 2; mi++)
                #pragma unroll
                for (int ni = 0; ni < 8; ni++)
                    MMA_BF16(c[mi][ni], a[mi], bfr[ni]);
        }
        __syncthreads();
    }

    // epilogue
    const int tg = lane & 3, gidr = lane >> 2;
    if (MODE == 0) {
        const float scale = 0.0625f;
        float* Sb = g_S + (size_t)b * TN * TN;
        #pragma unroll
        for (int mi = 0; mi < 2; mi++) {
            #pragma unroll
            for (int half = 0; half < 2; half++) {
                int m = m0 + warp_m * 32 + mi * 16 + gidr + half * 8;
                float* rowp = Sb + (size_t)m * TN + n0 + warp_n * 64 + tg * 2;
                #pragma unroll
                for (int ni = 0; ni < 8; ni++) {
                    float2 v;
                    v.x = c[mi][ni][half * 2 + 0] * scale;
                    v.y = c[mi][ni][half * 2 + 1] * scale;
                    *(float2*)(rowp + ni * 8) = v;
                }
            }
        }
    } else {
        #pragma unroll
        for (int mi = 0; mi < 2; mi++) {
            #pragma unroll
            for (int half = 0; half < 2; half++) {
                int m = m0 + warp_m * 32 + mi * 16 + gidr + half * 8;
                int t = m >> 10, rr = m & 1023;
                int hh = rr >> 5, ww = rr & 31;
                int f = b * TT + t;
                float* fb = g_feat + ((size_t)f * CC << 12);
                #pragma unroll
                for (int ni = 0; ni < 8; ni++) {
                    #pragma unroll
                    for (int q = 0; q < 2; q++) {
                        int dc = n0 + warp_n * 64 + ni * 8 + tg * 2 + q;
                        int ch = dc >> 2, ph = (dc >> 1) & 1, pw = dc & 1;
                        fb[((size_t)ch << 12) + (((hh << 1) + ph) << 6) + ((ww << 1) + pw)]
                            = c[mi][ni][half * 2 + q];
                    }
                }
            }
        }
    }
}

// ---------------- K3: row softmax over S -> bf16 hi/lo ----------------
__global__ void softmax_kernel() {
    size_t row = blockIdx.x;
    float* p = g_S + row * (size_t)TN;
    bf16* ph_out = g_S_hi + row * (size_t)TN;
    bf16* pl_out = g_S_lo + row * (size_t)TN;
    int tid = threadIdx.x;
    float vals[20];
    float m = -1e30f;
    #pragma unroll
    for (int i = 0; i < 20; i++) {
        vals[i] = p[tid + (i << 8)];
        m = fmaxf(m, vals[i]);
    }
    __shared__ float red[8];
    #pragma unroll
    for (int o = 16; o; o >>= 1) m = fmaxf(m, __shfl_xor_sync(0xffffffffu, m, o));
    if ((tid & 31) == 0) red[tid >> 5] = m;
    __syncthreads();
    m = red[0];
    #pragma unroll
    for (int i = 1; i < 8; i++) m = fmaxf(m, red[i]);
    __syncthreads();

    float s = 0.f;
    #pragma unroll
    for (int i = 0; i < 20; i++) {
        vals[i] = __expf(vals[i] - m);
        s += vals[i];
    }
    #pragma unroll
    for (int o = 16; o; o >>= 1) s += __shfl_xor_sync(0xffffffffu, s, o);
    if ((tid & 31) == 0) red[tid >> 5] = s;
    __syncthreads();
    s = 0.f;
    #pragma unroll
    for (int i = 0; i < 8; i++) s += red[i];
    float inv = 1.f / s;
    #pragma unroll
    for (int i = 0; i < 20; i++) {
        float v = vals[i] * inv;
        bf16 h = __float2bfloat16(v);
        ph_out[tid + (i << 8)] = h;
        pl_out[tid + (i << 8)] = __float2bfloat16(v - __bfloat162float(h));
    }
}

// ---------------- launch ----------------
extern "C" void kernel_launch(void* const* d_in, const int* in_sizes, int n_in,
                              void* d_out, int out_size) {
    const float* x  = (const float*)d_in[0];
    const float* wq = (const float*)d_in[1];
    const float* bq = (const float*)d_in[2];
    const float* wk = (const float*)d_in[3];
    const float* bk = (const float*)d_in[4];
    const float* wv = (const float*)d_in[5];
    const float* bv = (const float*)d_in[6];
    const float* wc = (const float*)d_in[7];
    const float* bc = (const float*)d_in[8];
    float* out = (float*)d_out;

    cudaFuncSetAttribute(dense_conv_kernel,
                         cudaFuncAttributeMaxDynamicSharedMemorySize, CONV_SMEM);

    int total = FF * CC * HH * WW;
    qk_conv_kernel<<<total / 256, 256>>>(x, wq, bq, wk, bk);
    dense_conv_kernel<<<dim3(4, 4, FF), dim3(16, 16), CONV_SMEM>>>(x, wv, bv, nullptr, nullptr, 1);
    hmma_gemm_kernel<0><<<dim3(40, 40, BB), 256>>>();
    softmax_kernel<<<BB * TN, 256>>>();
    hmma_gemm_kernel<1><<<dim3(2, 40, BB), 256>>>();
    dense_conv_kernel<<<dim3(4, 4, FF), dim3(16, 16), CONV_SMEM>>>(nullptr, wc, bc, x, out, 0);
}

// round 11
// speedup vs baseline: 3.2558x; 2.6138x over previous
#include <cuda_runtime.h>
#include <cuda_bf16.h>
#include <cstdint>

#define BB 2
#define TT 5
#define CC 64
#define HH 64
#define WW 64
#define FF 10          // BB*TT frames
#define DD 256         // token dim
#define NTOK 1024      // tokens per frame
#define TN 5120        // TT*NTOK

#define PADW 66
#define XPF (PADW * PADW * CC)      // halves per frame in padded buffer

typedef __nv_bfloat16 bf16;

// ---------------- scratch (device globals; no allocation) ----------------
__device__ __align__(1024) bf16  g_uq_hi[(size_t)BB * TN * DD];   // [b][tok][d]
__device__ __align__(1024) bf16  g_uq_lo[(size_t)BB * TN * DD];
__device__ __align__(1024) bf16  g_uk_hi[(size_t)BB * TN * DD];
__device__ __align__(1024) bf16  g_uk_lo[(size_t)BB * TN * DD];
__device__ __align__(1024) bf16  g_uv_hi[(size_t)BB * DD * TN];   // [b][d][tok]
__device__ __align__(1024) bf16  g_uv_lo[(size_t)BB * DD * TN];
__device__ __align__(1024) float g_S[(size_t)BB * TN * TN];       // fp32 logits (210MB)
__device__ __align__(1024) bf16  g_S_hi[(size_t)BB * TN * TN];    // softmax probs hi
__device__ __align__(1024) bf16  g_S_lo[(size_t)BB * TN * TN];    // softmax probs lo
__device__ __align__(1024) float g_feat[(size_t)FF * CC * HH * WW];
__device__ __align__(1024) bf16  g_xp_hi[(size_t)FF * XPF];       // padded input, chan-contig
__device__ __align__(1024) bf16  g_xp_lo[(size_t)FF * XPF];
__device__ __align__(1024) bf16  g_wb_hi[9 * CC * CC];            // [shift][co][ci]
__device__ __align__(1024) bf16  g_wb_lo[9 * CC * CC];

// ---------------- PTX helpers (sm_80+ feature set ONLY) ----------------
__device__ __forceinline__ uint32_t smem_u32(const void* p) {
    uint32_t a;
    asm("{ .reg .u64 t; cvta.to.shared.u64 t, %1; cvt.u32.u64 %0, t; }" : "=r"(a) : "l"(p));
    return a;
}
#define CP_ASYNC16(saddr, gptr) \
    asm volatile("cp.async.cg.shared.global [%0], [%1], 16;" :: "r"(saddr), "l"(gptr))
#define CP_COMMIT() asm volatile("cp.async.commit_group;" ::: "memory")
#define CP_WAIT0()  asm volatile("cp.async.wait_group 0;" ::: "memory")
#define CP_WAIT1()  asm volatile("cp.async.wait_group 1;" ::: "memory")

#define LDMATRIX_X4(r0, r1, r2, r3, addr) \
    asm volatile("ldmatrix.sync.aligned.m8n8.x4.shared.b16 {%0,%1,%2,%3}, [%4];" \
        : "=r"(r0), "=r"(r1), "=r"(r2), "=r"(r3) : "r"(addr))

#define MMA_BF16(c, a, b) \
    asm volatile("mma.sync.aligned.m16n8k16.row.col.f32.bf16.bf16.f32 " \
        "{%0,%1,%2,%3}, {%4,%5,%6,%7}, {%8,%9}, {%0,%1,%2,%3};" \
        : "+f"((c)[0]), "+f"((c)[1]), "+f"((c)[2]), "+f"((c)[3]) \
        : "r"((a)[0]), "r"((a)[1]), "r"((a)[2]), "r"((a)[3]), "r"((b)[0]), "r"((b)[1]))

// ---------------- K0a: zero padded buffers (borders must stay 0) ----------------
__global__ void zero_xp_kernel() {
    const int n16 = (FF * XPF * 2) / 16;   // uint4 count per buffer
    int i = blockIdx.x * blockDim.x + threadIdx.x;
    uint4 z = {0, 0, 0, 0};
    if (i < n16) ((uint4*)g_xp_hi)[i] = z;
    else if (i < 2 * n16) ((uint4*)g_xp_lo)[i - n16] = z;
}

// ---------------- K0b: weight split [co][ci][3][3] -> [sh][co][ci] hi/lo ----------------
__global__ void wsplit_kernel(const float* __restrict__ w) {
    int i = blockIdx.x * blockDim.x + threadIdx.x;
    if (i >= 9 * CC * CC) return;
    int sh = i / (CC * CC);
    int rem = i - sh * CC * CC;          // co*64+ci
    float v = w[(size_t)rem * 9 + sh];
    bf16 h = __float2bfloat16(v);
    g_wb_hi[i] = h;
    g_wb_lo[i] = __float2bfloat16(v - __bfloat162float(h));
}

// ---------------- K0c: pad + transpose + split: src[f][c][64][64] -> xp[f][py][px][c] ----------------
__global__ void pad_split_kernel(const float* __restrict__ src_ext, int use_feat) {
    __shared__ float tile[CC][65];
    const float* src = use_feat ? g_feat : src_ext;
    int f = blockIdx.y, y = blockIdx.x;
    int tid = threadIdx.x;
    for (int e = tid; e < CC * 64; e += 256) {
        int c = e >> 6, xc = e & 63;
        tile[c][xc] = src[(((size_t)f * CC + c) << 12) + (y << 6) + xc];
    }
    __syncthreads();
    size_t base = (size_t)f * XPF + ((size_t)(y + 1) * PADW + 1) * CC;
    for (int e = tid; e < CC * 64; e += 256) {
        int xc = e >> 6, c = e & 63;
        float v = tile[c][xc];
        bf16 h = __float2bfloat16(v);
        g_xp_hi[base + (size_t)xc * CC + c] = h;
        g_xp_lo[base + (size_t)xc * CC + c] = __float2bfloat16(v - __bfloat162float(h));
    }
}

// ---------------- K1: depthwise q & k conv -> bf16 hi/lo token layout ----------------
__global__ void qk_conv_kernel(const float* __restrict__ x,
                               const float* __restrict__ wq, const float* __restrict__ bq,
                               const float* __restrict__ wk, const float* __restrict__ bk) {
    int idx = blockIdx.x * blockDim.x + threadIdx.x;
    if (idx >= FF * CC * HH * WW) return;
    int col = idx & 63;
    int row = (idx >> 6) & 63;
    int ch  = (idx >> 12) & 63;
    int f   = idx >> 18;

    const float* xp = x + (((size_t)f * CC + ch) << 12);
    float accq = bq[ch];
    float acck = bk[ch];
    const float* wqp = wq + ch * 9;
    const float* wkp = wk + ch * 9;
    #pragma unroll
    for (int ky = 0; ky < 3; ky++) {
        int r = row + ky - 1;
        if (r < 0 || r >= HH) continue;
        #pragma unroll
        for (int kx = 0; kx < 3; kx++) {
            int c2 = col + kx - 1;
            if (c2 < 0 || c2 >= WW) continue;
            float v = xp[(r << 6) + c2];
            accq += v * wqp[ky * 3 + kx];
            acck += v * wkp[ky * 3 + kx];
        }
    }
    int b = f / TT, t = f % TT;
    int hh = row >> 1, ph = row & 1, ww = col >> 1, pw = col & 1;
    int dch = ch * 4 + ph * 2 + pw;
    int tok = t * NTOK + hh * 32 + ww;
    size_t o = ((size_t)b * TN + tok) * DD + dch;
    bf16 hq = __float2bfloat16(accq);
    bf16 hk = __float2bfloat16(acck);
    g_uq_hi[o] = hq;
    g_uq_lo[o] = __float2bfloat16(accq - __bfloat162float(hq));
    g_uk_hi[o] = hk;
    g_uk_lo[o] = __float2bfloat16(acck - __bfloat162float(hk));
}

// ---------------- conv as 9-shift HMMA GEMM ----------------
// Tile: M=128 pixels (2 output rows) x N=64 co. 27 iters: 9 shifts x 3 segments, K=64.
// MODE 0: v conv -> uv hi/lo tokenized. MODE 1: out conv + bias + residual -> out.
#define CPITCH 144
#define CABUF  (128 * CPITCH)      // 18432
#define CBBUF  (64 * CPITCH)       // 9216
#define CONVMMA_SMEM (2 * CABUF + 2 * CBBUF)   // 55296

template <int MODE>
__global__ void __launch_bounds__(256)
conv_mma_kernel(const float* __restrict__ bias,
                const float* __restrict__ resid,
                float* __restrict__ outp) {
    extern __shared__ __align__(128) char csm[];
    const int tid = threadIdx.x;
    const int lane = tid & 31, wid = tid >> 5;
    const int warp_m = wid & 3, warp_n = wid >> 2;     // 4 x 2
    const int f  = blockIdx.y;
    const int y0 = blockIdx.x * 2;                     // 2 output rows per tile

    const char* xH = (const char*)g_xp_hi + (size_t)f * XPF * 2;
    const char* xL = (const char*)g_xp_lo + (size_t)f * XPF * 2;
    const uint32_t sb = smem_u32(csm);

    auto load_chunk = [&](int it) {
        const int sh = it / 3, seg = it - sh * 3;
        const int dy = sh / 3, dx = sh - dy * 3;
        const char* aS = ((seg == 1) ? xL : xH) + ((size_t)(y0 + dy) * PADW + dx) * 128;
        const char* bS = (const char*)((seg == 2) ? g_wb_lo : g_wb_hi) + (size_t)sh * CC * CC * 2;
        const uint32_t sa = sb + (it & 1) * CABUF;
        const uint32_t sbm = sb + 2 * CABUF + (it & 1) * CBBUF;
        #pragma unroll
        for (int u = 0; u < 4; u++) {
            int e = tid + u * 256;                 // 0..1023
            int pix = e >> 3, c16 = (e & 7) << 4;
            CP_ASYNC16(sa + pix * CPITCH + c16,
                       aS + (size_t)((pix >> 6) * PADW + (pix & 63)) * 128 + c16);
        }
        #pragma unroll
        for (int u = 0; u < 2; u++) {
            int e = tid + u * 256;                 // 0..511
            int co = e >> 3, c16 = (e & 7) << 4;
            CP_ASYNC16(sbm + co * CPITCH + c16, bS + (size_t)co * 128 + c16);
        }
        CP_COMMIT();
    };

    float c[2][4][4];
    #pragma unroll
    for (int i = 0; i < 2; i++)
        #pragma unroll
        for (int j = 0; j < 4; j++)
            #pragma unroll
            for (int r = 0; r < 4; r++) c[i][j][r] = 0.f;

    const int lrow = lane & 7;
    const int lg   = lane >> 3;
    const int rowAdd = (lg & 1) * 8;
    const int chunk16 = (lg >> 1) * 16;

    load_chunk(0);

    #pragma unroll 1
    for (int it = 0; it < 27; it++) {
        if (it + 1 < 27) { load_chunk(it + 1); CP_WAIT1(); } else { CP_WAIT0(); }
        __syncthreads();
        const uint32_t sa = sb + (it & 1) * CABUF;
        const uint32_t sbm = sb + 2 * CABUF + (it & 1) * CBBUF;
        #pragma unroll
        for (int s = 0; s < 4; s++) {
            const int sByte = s * 32;
            uint32_t a[2][4];
            #pragma unroll
            for (int mi = 0; mi < 2; mi++) {
                int r = warp_m * 32 + mi * 16 + lrow + rowAdd;
                LDMATRIX_X4(a[mi][0], a[mi][1], a[mi][2], a[mi][3],
                            sa + r * CPITCH + sByte + chunk16);
            }
            uint32_t bfr[4][2];
            #pragma unroll
            for (int ff = 0; ff < 2; ff++) {
                int r = warp_n * 32 + ff * 16 + lrow + rowAdd;
                uint32_t r0, r1, r2, r3;
                LDMATRIX_X4(r0, r1, r2, r3, sbm + r * CPITCH + sByte + chunk16);
                bfr[2 * ff][0] = r0; bfr[2 * ff][1] = r2;
                bfr[2 * ff + 1][0] = r1; bfr[2 * ff + 1][1] = r3;
            }
            #pragma unroll
            for (int mi = 0; mi < 2; mi++)
                #pragma unroll
                for (int ni = 0; ni < 4; ni++)
                    MMA_BF16(c[mi][ni], a[mi], bfr[ni]);
        }
        __syncthreads();
    }

    // epilogue
    const int tg = lane & 3, gidr = lane >> 2;
    #pragma unroll
    for (int mi = 0; mi < 2; mi++) {
        #pragma unroll
        for (int half = 0; half < 2; half++) {
            int p = warp_m * 32 + mi * 16 + gidr + half * 8;   // pixel 0..127
            int y = y0 + (p >> 6), xc = p & 63;
            #pragma unroll
            for (int ni = 0; ni < 4; ni++) {
                #pragma unroll
                for (int q = 0; q < 2; q++) {
                    int co = warp_n * 32 + ni * 8 + tg * 2 + q;
                    float val = c[mi][ni][half * 2 + q] + __ldg(bias + co);
                    if (MODE == 0) {
                        int b = f / TT, t = f % TT;
                        int hh = y >> 1, ph = y & 1, ww = xc >> 1, pw = xc & 1;
                        int dch = co * 4 + ph * 2 + pw;
                        int tok = t * NTOK + hh * 32 + ww;
                        size_t o = ((size_t)b * DD + dch) * TN + tok;
                        bf16 h = __float2bfloat16(val);
                        g_uv_hi[o] = h;
                        g_uv_lo[o] = __float2bfloat16(val - __bfloat162float(h));
                    } else {
                        size_t oi = (((size_t)f * CC + co) << 12) + (y << 6) + xc;
                        outp[oi] = val + resid[oi];
                    }
                }
            }
        }
    }
}

// ---------------- split-bf16 HMMA GEMM (attention) ----------------
#define PITCHB 80
#define ABUF   10240

template <int MODE>
__global__ void __launch_bounds__(256)
hmma_gemm_kernel() {
    __shared__ __align__(128) char gsm[40960];
    const int tid = threadIdx.x;
    const int lane = tid & 31, wid = tid >> 5;
    const int warp_m = wid & 3, warp_n = wid >> 2;
    const int b  = blockIdx.z;
    const int m0 = blockIdx.y * 128;
    const int n0 = blockIdx.x * 128;

    constexpr int KC = (MODE == 0) ? 8 : 160;
    constexpr int NIT = 3 * KC;
    const size_t aRowB = (MODE == 0) ? DD * 2 : TN * 2;
    const size_t bRowB = (MODE == 0) ? DD * 2 : TN * 2;

    const char *aH, *aL, *bH, *bL;
    if (MODE == 0) {
        size_t ao = ((size_t)b * TN + m0) * DD * 2;
        size_t bo = ((size_t)b * TN + n0) * DD * 2;
        aH = (const char*)g_uq_hi + ao;  aL = (const char*)g_uq_lo + ao;
        bH = (const char*)g_uk_hi + bo;  bL = (const char*)g_uk_lo + bo;
    } else {
        size_t ao = ((size_t)b * TN + m0) * TN * 2;
        size_t bo = ((size_t)b * DD + n0) * TN * 2;
        aH = (const char*)g_S_hi + ao;   aL = (const char*)g_S_lo + ao;
        bH = (const char*)g_uv_hi + bo;  bL = (const char*)g_uv_lo + bo;
    }

    const uint32_t sb = smem_u32(gsm);

    auto load_chunk = [&](int it) {
        const int seg = it / KC, kc = it - seg * KC;
        const char* aS = (seg == 1) ? aL : aH;
        const char* bS = (seg == 2) ? bL : bH;
        const uint32_t sa = sb + (it & 1) * ABUF;
        const uint32_t sbm = sb + 20480 + (it & 1) * ABUF;
        const size_t kOff = (size_t)kc * 64;
        #pragma unroll
        for (int u = 0; u < 2; u++) {
            int e = tid + u * 256;
            int row = e >> 2, c16 = (e & 3) << 4;
            CP_ASYNC16(sa + row * PITCHB + c16, aS + (size_t)row * aRowB + kOff + c16);
            CP_ASYNC16(sbm + row * PITCHB + c16, bS + (size_t)row * bRowB + kOff + c16);
        }
        CP_COMMIT();
    };

    float c[2][8][4];
    #pragma unroll
    for (int i = 0; i < 2; i++)
        #pragma unroll
        for (int j = 0; j < 8; j++)
            #pragma unroll
            for (int r = 0; r < 4; r++) c[i][j][r] = 0.f;

    const int lrow = lane & 7;
    const int lg   = lane >> 3;
    const int rowAdd = (lg & 1) * 8;
    const int chunk16 = (lg >> 1) * 16;

    load_chunk(0);

    #pragma unroll 1
    for (int it = 0; it < NIT; it++) {
        if (it + 1 < NIT) { load_chunk(it + 1); CP_WAIT1(); } else { CP_WAIT0(); }
        __syncthreads();

        const uint32_t sa = sb + (it & 1) * ABUF;
        const uint32_t sbm = sb + 20480 + (it & 1) * ABUF;
        #pragma unroll
        for (int s = 0; s < 2; s++) {
            const int sByte = s * 32;
            uint32_t a[2][4];
            #pragma unroll
            for (int mi = 0; mi < 2; mi++) {
                int r = warp_m * 32 + mi * 16 + lrow + rowAdd;
                LDMATRIX_X4(a[mi][0], a[mi][1], a[mi][2], a[mi][3],
                            sa + r * PITCHB + sByte + chunk16);
            }
            uint32_t bfr[8][2];
            #pragma unroll
            for (int ff = 0; ff < 4; ff++) {
                int r = warp_n * 64 + ff * 16 + lrow + rowAdd;
                uint32_t r0, r1, r2, r3;
                LDMATRIX_X4(r0, r1, r2, r3, sbm + r * PITCHB + sByte + chunk16);
                bfr[2 * ff][0] = r0; bfr[2 * ff][1] = r2;
                bfr[2 * ff + 1][0] = r1; bfr[2 * ff + 1][1] = r3;
            }
            #pragma unroll
            for (int mi = 0; mi < 2; mi++)
                #pragma unroll
                for (int ni = 0; ni < 8; ni++)
                    MMA_BF16(c[mi][ni], a[mi], bfr[ni]);
        }
        __syncthreads();
    }

    const int tg = lane & 3, gidr = lane >> 2;
    if (MODE == 0) {
        const float scale = 0.0625f;
        float* Sb = g_S + (size_t)b * TN * TN;
        #pragma unroll
        for (int mi = 0; mi < 2; mi++) {
            #pragma unroll
            for (int half = 0; half < 2; half++) {
                int m = m0 + warp_m * 32 + mi * 16 + gidr + half * 8;
                float* rowp = Sb + (size_t)m * TN + n0 + warp_n * 64 + tg * 2;
                #pragma unroll
                for (int ni = 0; ni < 8; ni++) {
                    float2 v;
                    v.x = c[mi][ni][half * 2 + 0] * scale;
                    v.y = c[mi][ni][half * 2 + 1] * scale;
                    *(float2*)(rowp + ni * 8) = v;
                }
            }
        }
    } else {
        #pragma unroll
        for (int mi = 0; mi < 2; mi++) {
            #pragma unroll
            for (int half = 0; half < 2; half++) {
                int m = m0 + warp_m * 32 + mi * 16 + gidr + half * 8;
                int t = m >> 10, rr = m & 1023;
                int hh = rr >> 5, ww = rr & 31;
                int f = b * TT + t;
                float* fb = g_feat + ((size_t)f * CC << 12);
                #pragma unroll
                for (int ni = 0; ni < 8; ni++) {
                    #pragma unroll
                    for (int q = 0; q < 2; q++) {
                        int dc = n0 + warp_n * 64 + ni * 8 + tg * 2 + q;
                        int ch = dc >> 2, ph = (dc >> 1) & 1, pw = dc & 1;
                        fb[((size_t)ch << 12) + (((hh << 1) + ph) << 6) + ((ww << 1) + pw)]
                            = c[mi][ni][half * 2 + q];
                    }
                }
            }
        }
    }
}

// ---------------- K3: row softmax over S -> bf16 hi/lo ----------------
__global__ void softmax_kernel() {
    size_t row = blockIdx.x;
    float* p = g_S + row * (size_t)TN;
    bf16* ph_out = g_S_hi + row * (size_t)TN;
    bf16* pl_out = g_S_lo + row * (size_t)TN;
    int tid = threadIdx.x;
    float vals[20];
    float m = -1e30f;
    #pragma unroll
    for (int i = 0; i < 20; i++) {
        vals[i] = p[tid + (i << 8)];
        m = fmaxf(m, vals[i]);
    }
    __shared__ float red[8];
    #pragma unroll
    for (int o = 16; o; o >>= 1) m = fmaxf(m, __shfl_xor_sync(0xffffffffu, m, o));
    if ((tid & 31) == 0) red[tid >> 5] = m;
    __syncthreads();
    m = red[0];
    #pragma unroll
    for (int i = 1; i < 8; i++) m = fmaxf(m, red[i]);
    __syncthreads();

    float s = 0.f;
    #pragma unroll
    for (int i = 0; i < 20; i++) {
        vals[i] = __expf(vals[i] - m);
        s += vals[i];
    }
    #pragma unroll
    for (int o = 16; o; o >>= 1) s += __shfl_xor_sync(0xffffffffu, s, o);
    if ((tid & 31) == 0) red[tid >> 5] = s;
    __syncthreads();
    s = 0.f;
    #pragma unroll
    for (int i = 0; i < 8; i++) s += red[i];
    float inv = 1.f / s;
    #pragma unroll
    for (int i = 0; i < 20; i++) {
        float v = vals[i] * inv;
        bf16 h = __float2bfloat16(v);
        ph_out[tid + (i << 8)] = h;
        pl_out[tid + (i << 8)] = __float2bfloat16(v - __bfloat162float(h));
    }
}

// ---------------- launch ----------------
extern "C" void kernel_launch(void* const* d_in, const int* in_sizes, int n_in,
                              void* d_out, int out_size) {
    const float* x  = (const float*)d_in[0];
    const float* wq = (const float*)d_in[1];
    const float* bq = (const float*)d_in[2];
    const float* wk = (const float*)d_in[3];
    const float* bk = (const float*)d_in[4];
    const float* wv = (const float*)d_in[5];
    const float* bv = (const float*)d_in[6];
    const float* wc = (const float*)d_in[7];
    const float* bc = (const float*)d_in[8];
    float* out = (float*)d_out;

    cudaFuncSetAttribute(conv_mma_kernel<0>,
                         cudaFuncAttributeMaxDynamicSharedMemorySize, CONVMMA_SMEM);
    cudaFuncSetAttribute(conv_mma_kernel<1>,
                         cudaFuncAttributeMaxDynamicSharedMemorySize, CONVMMA_SMEM);

    const int nZero = 2 * (FF * XPF * 2) / 16;
    zero_xp_kernel<<<(nZero + 255) / 256, 256>>>();
    wsplit_kernel<<<(9 * CC * CC + 255) / 256, 256>>>(wv);
    pad_split_kernel<<<dim3(64, FF), 256>>>(x, 0);
    conv_mma_kernel<0><<<dim3(32, FF), 256, CONVMMA_SMEM>>>(bv, nullptr, nullptr);

    int total = FF * CC * HH * WW;
    qk_conv_kernel<<<total / 256, 256>>>(x, wq, bq, wk, bk);
    hmma_gemm_kernel<0><<<dim3(40, 40, BB), 256>>>();
    softmax_kernel<<<BB * TN, 256>>>();
    hmma_gemm_kernel<1><<<dim3(2, 40, BB), 256>>>();

    wsplit_kernel<<<(9 * CC * CC + 255) / 256, 256>>>(wc);
    pad_split_kernel<<<dim3(64, FF), 256>>>(nullptr, 1);
    conv_mma_kernel<1><<<dim3(32, FF), 256, CONVMMA_SMEM>>>(bc, x, out);
}

// round 12
// speedup vs baseline: 3.5891x; 1.1024x over previous
#include <cuda_runtime.h>
#include <cuda_bf16.h>
#include <cstdint>

#define BB 2
#define TT 5
#define CC 64
#define HH 64
#define WW 64
#define FF 10          // BB*TT frames
#define DD 256         // token dim
#define NTOK 1024      // tokens per frame
#define TN 5120        // TT*NTOK

#define PADW 66
#define XPF (PADW * PADW * CC)      // halves per frame in padded buffer

typedef __nv_bfloat16 bf16;

// ---------------- scratch (device globals; no allocation) ----------------
__device__ __align__(1024) bf16  g_uq_hi[(size_t)BB * TN * DD];   // [b][tok][d]
__device__ __align__(1024) bf16  g_uq_lo[(size_t)BB * TN * DD];
__device__ __align__(1024) bf16  g_uk_hi[(size_t)BB * TN * DD];
__device__ __align__(1024) bf16  g_uk_lo[(size_t)BB * TN * DD];
__device__ __align__(1024) bf16  g_uv_hi[(size_t)BB * DD * TN];   // [b][d][tok]
__device__ __align__(1024) bf16  g_uv_lo[(size_t)BB * DD * TN];
__device__ __align__(1024) float g_S[(size_t)BB * TN * TN];       // fp32 logits (210MB)
__device__ __align__(1024) bf16  g_S_hi[(size_t)BB * TN * TN];    // softmax probs hi
__device__ __align__(1024) bf16  g_S_lo[(size_t)BB * TN * TN];    // softmax probs lo
__device__ __align__(1024) float g_feat[(size_t)FF * CC * HH * WW];
__device__ __align__(1024) bf16  g_xp_hi[(size_t)FF * XPF];       // padded input, chan-contig
__device__ __align__(1024) bf16  g_xp_lo[(size_t)FF * XPF];
__device__ __align__(1024) bf16  g_wb_hi[9 * CC * CC];            // [shift][co][ci]
__device__ __align__(1024) bf16  g_wb_lo[9 * CC * CC];

// ---------------- PTX helpers (sm_80+ feature set ONLY) ----------------
__device__ __forceinline__ uint32_t smem_u32(const void* p) {
    uint32_t a;
    asm("{ .reg .u64 t; cvta.to.shared.u64 t, %1; cvt.u32.u64 %0, t; }" : "=r"(a) : "l"(p));
    return a;
}
#define CP_ASYNC16(saddr, gptr) \
    asm volatile("cp.async.cg.shared.global [%0], [%1], 16;" :: "r"(saddr), "l"(gptr))
#define CP_COMMIT() asm volatile("cp.async.commit_group;" ::: "memory")
#define CP_WAIT0()  asm volatile("cp.async.wait_group 0;" ::: "memory")
#define CP_WAIT1()  asm volatile("cp.async.wait_group 1;" ::: "memory")

#define LDMATRIX_X4(r0, r1, r2, r3, addr) \
    asm volatile("ldmatrix.sync.aligned.m8n8.x4.shared.b16 {%0,%1,%2,%3}, [%4];" \
        : "=r"(r0), "=r"(r1), "=r"(r2), "=r"(r3) : "r"(addr))

#define MMA_BF16(c, a, b) \
    asm volatile("mma.sync.aligned.m16n8k16.row.col.f32.bf16.bf16.f32 " \
        "{%0,%1,%2,%3}, {%4,%5,%6,%7}, {%8,%9}, {%0,%1,%2,%3};" \
        : "+f"((c)[0]), "+f"((c)[1]), "+f"((c)[2]), "+f"((c)[3]) \
        : "r"((a)[0]), "r"((a)[1]), "r"((a)[2]), "r"((a)[3]), "r"((b)[0]), "r"((b)[1]))

// ---------------- K0a: zero padded buffers (borders must stay 0) ----------------
__global__ void zero_xp_kernel() {
    const int n16 = (FF * XPF * 2) / 16;   // uint4 count per buffer
    int i = blockIdx.x * blockDim.x + threadIdx.x;
    uint4 z = {0, 0, 0, 0};
    if (i < n16) ((uint4*)g_xp_hi)[i] = z;
    else if (i < 2 * n16) ((uint4*)g_xp_lo)[i - n16] = z;
}

// ---------------- K0b: weight split [co][ci][3][3] -> [sh][co][ci] hi/lo ----------------
__global__ void wsplit_kernel(const float* __restrict__ w) {
    int i = blockIdx.x * blockDim.x + threadIdx.x;
    if (i >= 9 * CC * CC) return;
    int sh = i / (CC * CC);
    int rem = i - sh * CC * CC;          // co*64+ci
    float v = w[(size_t)rem * 9 + sh];
    bf16 h = __float2bfloat16(v);
    g_wb_hi[i] = h;
    g_wb_lo[i] = __float2bfloat16(v - __bfloat162float(h));
}

// ---------------- K0c: pad + transpose + split: src[f][c][64][64] -> xp[f][py][px][c] ----------------
__global__ void pad_split_kernel(const float* __restrict__ src_ext, int use_feat) {
    __shared__ float tile[CC][65];
    const float* src = use_feat ? g_feat : src_ext;
    int f = blockIdx.y, y = blockIdx.x;
    int tid = threadIdx.x;
    for (int e = tid; e < CC * 64; e += 256) {
        int c = e >> 6, xc = e & 63;
        tile[c][xc] = src[(((size_t)f * CC + c) << 12) + (y << 6) + xc];
    }
    __syncthreads();
    size_t base = (size_t)f * XPF + ((size_t)(y + 1) * PADW + 1) * CC;
    for (int e = tid; e < CC * 64; e += 256) {
        int xc = e >> 6, c = e & 63;
        float v = tile[c][xc];
        bf16 h = __float2bfloat16(v);
        g_xp_hi[base + (size_t)xc * CC + c] = h;
        g_xp_lo[base + (size_t)xc * CC + c] = __float2bfloat16(v - __bfloat162float(h));
    }
}

// ---------------- K1: depthwise q & k conv -> bf16 hi/lo token layout ----------------
__global__ void qk_conv_kernel(const float* __restrict__ x,
                               const float* __restrict__ wq, const float* __restrict__ bq,
                               const float* __restrict__ wk, const float* __restrict__ bk) {
    int idx = blockIdx.x * blockDim.x + threadIdx.x;
    if (idx >= FF * CC * HH * WW) return;
    int col = idx & 63;
    int row = (idx >> 6) & 63;
    int ch  = (idx >> 12) & 63;
    int f   = idx >> 18;

    const float* xp = x + (((size_t)f * CC + ch) << 12);
    float accq = bq[ch];
    float acck = bk[ch];
    const float* wqp = wq + ch * 9;
    const float* wkp = wk + ch * 9;
    #pragma unroll
    for (int ky = 0; ky < 3; ky++) {
        int r = row + ky - 1;
        if (r < 0 || r >= HH) continue;
        #pragma unroll
        for (int kx = 0; kx < 3; kx++) {
            int c2 = col + kx - 1;
            if (c2 < 0 || c2 >= WW) continue;
            float v = xp[(r << 6) + c2];
            accq += v * wqp[ky * 3 + kx];
            acck += v * wkp[ky * 3 + kx];
        }
    }
    int b = f / TT, t = f % TT;
    int hh = row >> 1, ph = row & 1, ww = col >> 1, pw = col & 1;
    int dch = ch * 4 + ph * 2 + pw;
    int tok = t * NTOK + hh * 32 + ww;
    size_t o = ((size_t)b * TN + tok) * DD + dch;
    bf16 hq = __float2bfloat16(accq);
    bf16 hk = __float2bfloat16(acck);
    g_uq_hi[o] = hq;
    g_uq_lo[o] = __float2bfloat16(accq - __bfloat162float(hq));
    g_uk_hi[o] = hk;
    g_uk_lo[o] = __float2bfloat16(acck - __bfloat162float(hk));
}

// ---------------- conv as 9-shift HMMA GEMM ----------------
// Tile: M=128 pixels (2 output rows) x N=64 co. 27 iters: 9 shifts x 3 segments, K=64.
// MODE 0: v conv -> uv hi/lo tokenized. MODE 1: out conv + bias + residual -> out.
#define CPITCH 144
#define CABUF  (128 * CPITCH)      // 18432
#define CBBUF  (64 * CPITCH)       // 9216
#define CONVMMA_SMEM (2 * CABUF + 2 * CBBUF)   // 55296

template <int MODE>
__global__ void __launch_bounds__(256)
conv_mma_kernel(const float* __restrict__ bias,
                const float* __restrict__ resid,
                float* __restrict__ outp) {
    extern __shared__ __align__(128) char csm[];
    const int tid = threadIdx.x;
    const int lane = tid & 31, wid = tid >> 5;
    const int warp_m = wid & 3, warp_n = wid >> 2;     // 4 x 2
    const int f  = blockIdx.y;
    const int y0 = blockIdx.x * 2;                     // 2 output rows per tile

    const char* xH = (const char*)g_xp_hi + (size_t)f * XPF * 2;
    const char* xL = (const char*)g_xp_lo + (size_t)f * XPF * 2;
    const uint32_t sb = smem_u32(csm);

    auto load_chunk = [&](int it) {
        const int sh = it / 3, seg = it - sh * 3;
        const int dy = sh / 3, dx = sh - dy * 3;
        const char* aS = ((seg == 1) ? xL : xH) + ((size_t)(y0 + dy) * PADW + dx) * 128;
        const char* bS = (const char*)((seg == 2) ? g_wb_lo : g_wb_hi) + (size_t)sh * CC * CC * 2;
        const uint32_t sa = sb + (it & 1) * CABUF;
        const uint32_t sbm = sb + 2 * CABUF + (it & 1) * CBBUF;
        #pragma unroll
        for (int u = 0; u < 4; u++) {
            int e = tid + u * 256;                 // 0..1023
            int pix = e >> 3, c16 = (e & 7) << 4;
            CP_ASYNC16(sa + pix * CPITCH + c16,
                       aS + (size_t)((pix >> 6) * PADW + (pix & 63)) * 128 + c16);
        }
        #pragma unroll
        for (int u = 0; u < 2; u++) {
            int e = tid + u * 256;                 // 0..511
            int co = e >> 3, c16 = (e & 7) << 4;
            CP_ASYNC16(sbm + co * CPITCH + c16, bS + (size_t)co * 128 + c16);
        }
        CP_COMMIT();
    };

    float c[2][4][4];
    #pragma unroll
    for (int i = 0; i < 2; i++)
        #pragma unroll
        for (int j = 0; j < 4; j++)
            #pragma unroll
            for (int r = 0; r < 4; r++) c[i][j][r] = 0.f;

    const int lrow = lane & 7;
    const int lg   = lane >> 3;
    const int rowAdd = (lg & 1) * 8;
    const int chunk16 = (lg >> 1) * 16;

    load_chunk(0);

    #pragma unroll 1
    for (int it = 0; it < 27; it++) {
        if (it + 1 < 27) { load_chunk(it + 1); CP_WAIT1(); } else { CP_WAIT0(); }
        __syncthreads();
        const uint32_t sa = sb + (it & 1) * CABUF;
        const uint32_t sbm = sb + 2 * CABUF + (it & 1) * CBBUF;
        #pragma unroll
        for (int s = 0; s < 4; s++) {
            const int sByte = s * 32;
            uint32_t a[2][4];
            #pragma unroll
            for (int mi = 0; mi < 2; mi++) {
                int r = warp_m * 32 + mi * 16 + lrow + rowAdd;
                LDMATRIX_X4(a[mi][0], a[mi][1], a[mi][2], a[mi][3],
                            sa + r * CPITCH + sByte + chunk16);
            }
            uint32_t bfr[4][2];
            #pragma unroll
            for (int ff = 0; ff < 2; ff++) {
                int r = warp_n * 32 + ff * 16 + lrow + rowAdd;
                uint32_t r0, r1, r2, r3;
                LDMATRIX_X4(r0, r1, r2, r3, sbm + r * CPITCH + sByte + chunk16);
                bfr[2 * ff][0] = r0; bfr[2 * ff][1] = r2;
                bfr[2 * ff + 1][0] = r1; bfr[2 * ff + 1][1] = r3;
            }
            #pragma unroll
            for (int mi = 0; mi < 2; mi++)
                #pragma unroll
                for (int ni = 0; ni < 4; ni++)
                    MMA_BF16(c[mi][ni], a[mi], bfr[ni]);
        }
        __syncthreads();
    }

    // epilogue
    const int tg = lane & 3, gidr = lane >> 2;
    #pragma unroll
    for (int mi = 0; mi < 2; mi++) {
        #pragma unroll
        for (int half = 0; half < 2; half++) {
            int p = warp_m * 32 + mi * 16 + gidr + half * 8;   // pixel 0..127
            int y = y0 + (p >> 6), xc = p & 63;
            #pragma unroll
            for (int ni = 0; ni < 4; ni++) {
                #pragma unroll
                for (int q = 0; q < 2; q++) {
                    int co = warp_n * 32 + ni * 8 + tg * 2 + q;
                    float val = c[mi][ni][half * 2 + q] + __ldg(bias + co);
                    if (MODE == 0) {
                        int b = f / TT, t = f % TT;
                        int hh = y >> 1, ph = y & 1, ww = xc >> 1, pw = xc & 1;
                        int dch = co * 4 + ph * 2 + pw;
                        int tok = t * NTOK + hh * 32 + ww;
                        size_t o = ((size_t)b * DD + dch) * TN + tok;
                        bf16 h = __float2bfloat16(val);
                        g_uv_hi[o] = h;
                        g_uv_lo[o] = __float2bfloat16(val - __bfloat162float(h));
                    } else {
                        size_t oi = (((size_t)f * CC + co) << 12) + (y << 6) + xc;
                        outp[oi] = val + resid[oi];
                    }
                }
            }
        }
    }
}

// ---------------- split-bf16 HMMA GEMM (attention), K-chunk 64 ----------------
#define GPITCH 144                  // 64 data halves (128B) + 8 pad halves
#define GABUF  (128 * GPITCH)       // 18432
#define GEMM_SMEM_SZ (4 * GABUF)    // 73728: A0,A1,B0,B1

template <int MODE>
__global__ void __launch_bounds__(256)
hmma_gemm_kernel() {
    extern __shared__ __align__(128) char gsm[];
    const int tid = threadIdx.x;
    const int lane = tid & 31, wid = tid >> 5;
    const int warp_m = wid & 3, warp_n = wid >> 2;
    const int b  = blockIdx.z;
    const int m0 = blockIdx.y * 128;
    const int n0 = blockIdx.x * 128;

    constexpr int KC = (MODE == 0) ? 4 : 80;   // K-chunks of 64 per segment
    constexpr int NIT = 3 * KC;
    const size_t aRowB = (MODE == 0) ? DD * 2 : TN * 2;
    const size_t bRowB = (MODE == 0) ? DD * 2 : TN * 2;

    const char *aH, *aL, *bH, *bL;
    if (MODE == 0) {
        size_t ao = ((size_t)b * TN + m0) * DD * 2;
        size_t bo = ((size_t)b * TN + n0) * DD * 2;
        aH = (const char*)g_uq_hi + ao;  aL = (const char*)g_uq_lo + ao;
        bH = (const char*)g_uk_hi + bo;  bL = (const char*)g_uk_lo + bo;
    } else {
        size_t ao = ((size_t)b * TN + m0) * TN * 2;
        size_t bo = ((size_t)b * DD + n0) * TN * 2;
        aH = (const char*)g_S_hi + ao;   aL = (const char*)g_S_lo + ao;
        bH = (const char*)g_uv_hi + bo;  bL = (const char*)g_uv_lo + bo;
    }

    const uint32_t sb = smem_u32(gsm);

    auto load_chunk = [&](int it) {
        const int seg = it / KC, kc = it - seg * KC;
        const char* aS = (seg == 1) ? aL : aH;
        const char* bS = (seg == 2) ? bL : bH;
        const uint32_t sa = sb + (it & 1) * GABUF;
        const uint32_t sbm = sb + 2 * GABUF + (it & 1) * GABUF;
        const size_t kOff = (size_t)kc * 128;
        #pragma unroll
        for (int u = 0; u < 4; u++) {
            int e = tid + u * 256;                 // 0..1023
            int row = e >> 3, c16 = (e & 7) << 4;
            CP_ASYNC16(sa + row * GPITCH + c16, aS + (size_t)row * aRowB + kOff + c16);
            CP_ASYNC16(sbm + row * GPITCH + c16, bS + (size_t)row * bRowB + kOff + c16);
        }
        CP_COMMIT();
    };

    float c[2][8][4];
    #pragma unroll
    for (int i = 0; i < 2; i++)
        #pragma unroll
        for (int j = 0; j < 8; j++)
            #pragma unroll
            for (int r = 0; r < 4; r++) c[i][j][r] = 0.f;

    const int lrow = lane & 7;
    const int lg   = lane >> 3;
    const int rowAdd = (lg & 1) * 8;
    const int chunk16 = (lg >> 1) * 16;

    load_chunk(0);

    #pragma unroll 1
    for (int it = 0; it < NIT; it++) {
        if (it + 1 < NIT) { load_chunk(it + 1); CP_WAIT1(); } else { CP_WAIT0(); }
        __syncthreads();

        const uint32_t sa = sb + (it & 1) * GABUF;
        const uint32_t sbm = sb + 2 * GABUF + (it & 1) * GABUF;
        #pragma unroll
        for (int s = 0; s < 4; s++) {
            const int sByte = s * 32;
            uint32_t a[2][4];
            #pragma unroll
            for (int mi = 0; mi < 2; mi++) {
                int r = warp_m * 32 + mi * 16 + lrow + rowAdd;
                LDMATRIX_X4(a[mi][0], a[mi][1], a[mi][2], a[mi][3],
                            sa + r * GPITCH + sByte + chunk16);
            }
            uint32_t bfr[8][2];
            #pragma unroll
            for (int ff = 0; ff < 4; ff++) {
                int r = warp_n * 64 + ff * 16 + lrow + rowAdd;
                uint32_t r0, r1, r2, r3;
                LDMATRIX_X4(r0, r1, r2, r3, sbm + r * GPITCH + sByte + chunk16);
                bfr[2 * ff][0] = r0; bfr[2 * ff][1] = r2;
                bfr[2 * ff + 1][0] = r1; bfr[2 * ff + 1][1] = r3;
            }
            #pragma unroll
            for (int mi = 0; mi < 2; mi++)
                #pragma unroll
                for (int ni = 0; ni < 8; ni++)
                    MMA_BF16(c[mi][ni], a[mi], bfr[ni]);
        }
        __syncthreads();
    }

    const int tg = lane & 3, gidr = lane >> 2;
    if (MODE == 0) {
        const float scale = 0.0625f;
        float* Sb = g_S + (size_t)b * TN * TN;
        #pragma unroll
        for (int mi = 0; mi < 2; mi++) {
            #pragma unroll
            for (int half = 0; half < 2; half++) {
                int m = m0 + warp_m * 32 + mi * 16 + gidr + half * 8;
                float* rowp = Sb + (size_t)m * TN + n0 + warp_n * 64 + tg * 2;
                #pragma unroll
                for (int ni = 0; ni < 8; ni++) {
                    float2 v;
                    v.x = c[mi][ni][half * 2 + 0] * scale;
                    v.y = c[mi][ni][half * 2 + 1] * scale;
                    *(float2*)(rowp + ni * 8) = v;
                }
            }
        }
    } else {
        #pragma unroll
        for (int mi = 0; mi < 2; mi++) {
            #pragma unroll
            for (int half = 0; half < 2; half++) {
                int m = m0 + warp_m * 32 + mi * 16 + gidr + half * 8;
                int t = m >> 10, rr = m & 1023;
                int hh = rr >> 5, ww = rr & 31;
                int f = b * TT + t;
                float* fb = g_feat + ((size_t)f * CC << 12);
                #pragma unroll
                for (int ni = 0; ni < 8; ni++) {
                    #pragma unroll
                    for (int q = 0; q < 2; q++) {
                        int dc = n0 + warp_n * 64 + ni * 8 + tg * 2 + q;
                        int ch = dc >> 2, ph = (dc >> 1) & 1, pw = dc & 1;
                        fb[((size_t)ch << 12) + (((hh << 1) + ph) << 6) + ((ww << 1) + pw)]
                            = c[mi][ni][half * 2 + q];
                    }
                }
            }
        }
    }
}

// ---------------- K3: row softmax over S -> bf16 hi/lo ----------------
__global__ void softmax_kernel() {
    size_t row = blockIdx.x;
    float* p = g_S + row * (size_t)TN;
    bf16* ph_out = g_S_hi + row * (size_t)TN;
    bf16* pl_out = g_S_lo + row * (size_t)TN;
    int tid = threadIdx.x;
    float vals[20];
    float m = -1e30f;
    #pragma unroll
    for (int i = 0; i < 20; i++) {
        vals[i] = p[tid + (i << 8)];
        m = fmaxf(m, vals[i]);
    }
    __shared__ float red[8];
    #pragma unroll
    for (int o = 16; o; o >>= 1) m = fmaxf(m, __shfl_xor_sync(0xffffffffu, m, o));
    if ((tid & 31) == 0) red[tid >> 5] = m;
    __syncthreads();
    m = red[0];
    #pragma unroll
    for (int i = 1; i < 8; i++) m = fmaxf(m, red[i]);
    __syncthreads();

    float s = 0.f;
    #pragma unroll
    for (int i = 0; i < 20; i++) {
        vals[i] = __expf(vals[i] - m);
        s += vals[i];
    }
    #pragma unroll
    for (int o = 16; o; o >>= 1) s += __shfl_xor_sync(0xffffffffu, s, o);
    if ((tid & 31) == 0) red[tid >> 5] = s;
    __syncthreads();
    s = 0.f;
    #pragma unroll
    for (int i = 0; i < 8; i++) s += red[i];
    float inv = 1.f / s;
    #pragma unroll
    for (int i = 0; i < 20; i++) {
        float v = vals[i] * inv;
        bf16 h = __float2bfloat16(v);
        ph_out[tid + (i << 8)] = h;
        pl_out[tid + (i << 8)] = __float2bfloat16(v - __bfloat162float(h));
    }
}

// ---------------- launch ----------------
extern "C" void kernel_launch(void* const* d_in, const int* in_sizes, int n_in,
                              void* d_out, int out_size) {
    const float* x  = (const float*)d_in[0];
    const float* wq = (const float*)d_in[1];
    const float* bq = (const float*)d_in[2];
    const float* wk = (const float*)d_in[3];
    const float* bk = (const float*)d_in[4];
    const float* wv = (const float*)d_in[5];
    const float* bv = (const float*)d_in[6];
    const float* wc = (const float*)d_in[7];
    const float* bc = (const float*)d_in[8];
    float* out = (float*)d_out;

    cudaFuncSetAttribute(conv_mma_kernel<0>,
                         cudaFuncAttributeMaxDynamicSharedMemorySize, CONVMMA_SMEM);
    cudaFuncSetAttribute(conv_mma_kernel<1>,
                         cudaFuncAttributeMaxDynamicSharedMemorySize, CONVMMA_SMEM);
    cudaFuncSetAttribute(hmma_gemm_kernel<0>,
                         cudaFuncAttributeMaxDynamicSharedMemorySize, GEMM_SMEM_SZ);
    cudaFuncSetAttribute(hmma_gemm_kernel<1>,
                         cudaFuncAttributeMaxDynamicSharedMemorySize, GEMM_SMEM_SZ);

    const int nZero = 2 * (FF * XPF * 2) / 16;
    zero_xp_kernel<<<(nZero + 255) / 256, 256>>>();
    wsplit_kernel<<<(9 * CC * CC + 255) / 256, 256>>>(wv);
    pad_split_kernel<<<dim3(64, FF), 256>>>(x, 0);
    conv_mma_kernel<0><<<dim3(32, FF), 256, CONVMMA_SMEM>>>(bv, nullptr, nullptr);

    int total = FF * CC * HH * WW;
    qk_conv_kernel<<<total / 256, 256>>>(x, wq, bq, wk, bk);
    hmma_gemm_kernel<0><<<dim3(40, 40, BB), 256, GEMM_SMEM_SZ>>>();
    softmax_kernel<<<BB * TN, 256>>>();
    hmma_gemm_kernel<1><<<dim3(2, 40, BB), 256, GEMM_SMEM_SZ>>>();

    wsplit_kernel<<<(9 * CC * CC + 255) / 256, 256>>>(wc);
    pad_split_kernel<<<dim3(64, FF), 256>>>(nullptr, 1);
    conv_mma_kernel<1><<<dim3(32, FF), 256, CONVMMA_SMEM>>>(bc, x, out);
}